// round 11
// baseline (speedup 1.0000x reference)
#include <cuda_runtime.h>
#include <math.h>
#include <stdint.h>

#define HD 512
#define BB 64
#define TK 512
#define NKN 256

// -------- scratch (device globals: no allocations allowed) --------
__device__ float g_dec[BB * HD];
__device__ float g_scores_tok[BB * TK];
__device__ float g_scores_node[BB * NKN];
__device__ float g_final[BB * TK];

// bf16 copies (packed pairs in uint32)
__device__ __align__(16) uint32_t g_bAtok[BB * TK * HD / 2];    // 33.5 MB
__device__ __align__(16) uint32_t g_bAnode[BB * NKN * HD / 2];  // 16.8 MB
__device__ __align__(16) uint32_t g_bWtok[HD * HD / 2];
__device__ __align__(16) uint32_t g_bWnode[HD * HD / 2];

__device__ __forceinline__ float fast_tanh(float x) {
    float y;
    asm("tanh.approx.f32 %0, %1;" : "=f"(y) : "f"(x));
    return y;
}

__device__ __forceinline__ uint32_t bfpack(float lo, float hi) {
    uint32_t r;
    asm("cvt.rn.bf16x2.f32 %0, %1, %2;" : "=r"(r) : "f"(hi), "f"(lo));
    return r;
}

__device__ __forceinline__ void cp16(uint32_t dst, const void* src) {
    asm volatile("cp.async.cg.shared.global [%0], [%1], 16;" :: "r"(dst), "l"(src));
}

// ---------------- K0: fp32 -> bf16 conversion + scratch zeroing ----------------
#define S0 (BB * TK * HD)     // 16777216
#define S1 (BB * NKN * HD)    // 8388608
#define S2 (HD * HD)          // 262144
#define CV_TOTAL ((size_t)S0 + S1 + 2 * S2)          // 25690112 floats
#define Z_DEC    (BB * HD)                            // 32768
#define Z_STOK   (BB * TK)                            // 32768
#define Z_SNODE  (BB * NKN)                           // 16384
#define Z_CT     (BB * HD)                            // 32768
#define Z_TOTAL  (Z_DEC + Z_STOK + Z_SNODE + Z_CT)    // 114688
__global__ void convert_kernel(const float* __restrict__ A_tok,
                               const float* __restrict__ A_node,
                               const float* __restrict__ Wt,
                               const float* __restrict__ Wn,
                               float* __restrict__ d_out) {
    size_t gid = (size_t)blockIdx.x * blockDim.x + threadIdx.x;
    size_t i8 = gid * 8;
    if (i8 >= CV_TOTAL) {
        size_t z = i8 - CV_TOTAL;
        float4 zf = make_float4(0.f, 0.f, 0.f, 0.f);
        float4* p;
        if (z < Z_DEC) p = (float4*)(g_dec + z);
        else if (z < Z_DEC + Z_STOK) p = (float4*)(g_scores_tok + (z - Z_DEC));
        else if (z < Z_DEC + Z_STOK + Z_SNODE)
            p = (float4*)(g_scores_node + (z - Z_DEC - Z_STOK));
        else p = (float4*)(d_out + (z - Z_DEC - Z_STOK - Z_SNODE));
        p[0] = zf;
        p[1] = zf;
        return;
    }
    const float4* s;
    uint4* d;
    if (i8 < S0) {
        s = (const float4*)(A_tok + i8);
        d = (uint4*)g_bAtok + (i8 >> 3);
    } else if (i8 < (size_t)S0 + S1) {
        size_t o = i8 - S0;
        s = (const float4*)(A_node + o);
        d = (uint4*)g_bAnode + (o >> 3);
    } else if (i8 < (size_t)S0 + S1 + S2) {
        size_t o = i8 - S0 - S1;
        s = (const float4*)(Wt + o);
        d = (uint4*)g_bWtok + (o >> 3);
    } else {
        size_t o = i8 - S0 - S1 - S2;
        s = (const float4*)(Wn + o);
        d = (uint4*)g_bWnode + (o >> 3);
    }
    float4 f0 = s[0], f1 = s[1];
    uint4 u;
    u.x = bfpack(f0.x, f0.y);
    u.y = bfpack(f0.z, f0.w);
    u.z = bfpack(f1.x, f1.y);
    u.w = bfpack(f1.z, f1.w);
    d[0] = u;
}

// ---------------- K1: dec_fea, k-split + batch-group ----------------
__global__ void dec_kernel2(const float* __restrict__ s_t,
                            const float* __restrict__ Wd,
                            const float* __restrict__ bd) {
    const int bg = blockIdx.x, kg = blockIdx.y;
    const int h = threadIdx.x;            // 512
    __shared__ float ss[8][128];
    for (int i = h; i < 8 * 128; i += 512) {
        int j = i >> 7, kk = i & 127;
        ss[j][kk] = s_t[(bg * 8 + j) * (2 * HD) + kg * 128 + kk];
    }
    __syncthreads();
    float acc[8];
    #pragma unroll
    for (int j = 0; j < 8; j++) acc[j] = 0.f;
    const float* Wp = Wd + (size_t)(kg * 128) * HD + h;
    #pragma unroll 4
    for (int kk = 0; kk < 128; kk++) {
        float w = Wp[(size_t)kk * HD];
        #pragma unroll
        for (int j = 0; j < 8; j++) acc[j] = fmaf(ss[j][kk], w, acc[j]);
    }
    float bias = (kg == 0) ? bd[h] : 0.f;
    #pragma unroll
    for (int j = 0; j < 8; j++)
        atomicAdd(&g_dec[(bg * 8 + j) * HD + h], acc[j] + bias);
}

// ---------------- K2: bf16 GEMM, A-resident N=512 stripe per CTA --------------
// grid = 384: bx<256 -> token M-tiles, bx>=256 -> node M-tiles. 512 threads.
// A 128x512 bf16 resident (128KB); B streamed 32 x 16KB tiles, 3-stage ring.
// Epilogue folds each 128-col chunk into rs regs; final smem reduce -> scores.
#define GA_BYTES (128 * 1024)          // A resident
#define GB_STG   (64 * 256)            // 16384 per stage
#define GOFF_DV  (GA_BYTES + 3 * GB_STG)          // 180224
#define GOFF_VV  (GOFF_DV + 2048)
#define GOFF_WC  (GOFF_VV + 2048)
#define GOFF_FLW (GOFF_WC + 2048)
#define GOFF_RED (GOFF_FLW + 512)
#define GSMEM    (GOFF_RED + 512)                 // 187392
__global__ void __launch_bounds__(512, 1)
gemm_score_fused(const float* __restrict__ flw,     // [B*NK]
                 const float* __restrict__ Wc,      // [512]
                 const float* __restrict__ v_tok,   // [512]
                 const float* __restrict__ v_node)  // [512]
{
    extern __shared__ char sm[];
    uint32_t sbase = (uint32_t)__cvta_generic_to_shared(sm);
    float* s_dv  = (float*)(sm + GOFF_DV);
    float* s_vv  = (float*)(sm + GOFF_VV);
    float* s_wc  = (float*)(sm + GOFF_WC);
    float* s_flw = (float*)(sm + GOFF_FLW);
    float* s_red = (float*)(sm + GOFF_RED);

    const int tid = threadIdx.x;
    const int lane = tid & 31, wid = tid >> 5;
    const int q = lane & 3, rr = lane >> 2;
    const int l15 = lane & 15, lh = lane >> 4;
    const int warp_m = wid & 3;        // 4 row groups of 32
    const int warp_n = wid >> 2;       // 4 col groups of 32 (within 128-chunk)
    const bool node = blockIdx.x >= 256;
    const int m0 = node ? (int)(blockIdx.x - 256) * 128 : (int)blockIdx.x * 128;
    const int b = node ? (m0 / NKN) : (m0 / TK);

    const uint16_t* gA = (const uint16_t*)(node ? g_bAnode : g_bAtok);
    const uint16_t* gW = (const uint16_t*)(node ? g_bWnode : g_bWtok);
    const float* v = node ? v_node : v_tok;

    // preload epilogue vectors into smem
    {
        s_dv[tid] = g_dec[b * HD + tid];
        s_vv[tid] = v[tid];
        s_wc[tid] = node ? Wc[tid] : 0.f;
        if (tid < 128) {
            s_flw[tid] = node ? flw[m0 + tid] : 0.f;
            s_red[tid] = 0.f;
        }
    }

    // A resident load: 128 rows x 64 chunks of 16B = 8192 chunks
    for (int i = 0; i < 16; i++) {
        int idx = tid + i * 512;
        int r = idx >> 6, cc = idx & 63;
        uint32_t off = r * 1024 + cc * 16;
        cp16(sbase + (off ^ ((r & 7) << 4)),
             gA + (size_t)(m0 + r) * HD + cc * 8);
    }
    asm volatile("cp.async.commit_group;" ::: "memory");

    auto load_B = [&](int g) {
        int s = g % 3;
        int kt = g & 7, n0 = (g >> 3) * 128;
        uint32_t sb = sbase + GA_BYTES + s * GB_STG;
        #pragma unroll
        for (int i = 0; i < 2; i++) {     // 64 rows x 16 chunks = 1024
            int idx = tid + i * 512;
            int r = idx >> 4, cc = idx & 15;
            uint32_t off = r * 256 + cc * 16;
            cp16(sb + (off ^ ((r & 15) << 4)),
                 gW + (size_t)(kt * 64 + r) * HD + n0 + cc * 8);
        }
        asm volatile("cp.async.commit_group;" ::: "memory");
    };

    load_B(0);
    load_B(1);

    float c[2][4][4];
    #pragma unroll
    for (int mt = 0; mt < 2; mt++)
        #pragma unroll
        for (int nt = 0; nt < 4; nt++)
            #pragma unroll
            for (int k = 0; k < 4; k++) c[mt][nt][k] = 0.f;
    float rs[2][2] = {};

    for (int g = 0; g < 32; g++) {
        int s = g % 3;
        if (g < 31) asm volatile("cp.async.wait_group 1;" ::: "memory");
        else        asm volatile("cp.async.wait_group 0;" ::: "memory");
        __syncthreads();
        if (g + 2 < 32) load_B(g + 2);

        const int kt = g & 7;
        uint32_t sB = sbase + GA_BYTES + s * GB_STG;

        #pragma unroll
        for (int kk = 0; kk < 4; kk++) {
            uint32_t bfr[2][4];
            int krow = kk * 16 + l15;
            uint32_t boff = (uint32_t)krow * 256 + warp_n * 64 + lh * 16;
            #pragma unroll
            for (int p = 0; p < 2; p++) {
                uint32_t addr = sB + ((boff + p * 32) ^ ((krow & 15) << 4));
                asm volatile(
                    "ldmatrix.sync.aligned.m8n8.x4.trans.shared.b16 {%0,%1,%2,%3}, [%4];"
                    : "=r"(bfr[p][0]), "=r"(bfr[p][1]),
                      "=r"(bfr[p][2]), "=r"(bfr[p][3]) : "r"(addr));
            }
            #pragma unroll
            for (int mt = 0; mt < 2; mt++) {
                int row = warp_m * 32 + mt * 16 + l15;
                uint32_t addr = sbase +
                    ((row * 1024 + kt * 128 + kk * 32 + lh * 16) ^ ((row & 7) << 4));
                uint32_t a[4];
                asm volatile(
                    "ldmatrix.sync.aligned.m8n8.x4.shared.b16 {%0,%1,%2,%3}, [%4];"
                    : "=r"(a[0]), "=r"(a[1]), "=r"(a[2]), "=r"(a[3]) : "r"(addr));
                #pragma unroll
                for (int nt = 0; nt < 4; nt++) {
                    uint32_t b0 = bfr[nt >> 1][(nt & 1) * 2];
                    uint32_t b1 = bfr[nt >> 1][(nt & 1) * 2 + 1];
                    asm volatile(
                        "mma.sync.aligned.m16n8k16.row.col.f32.bf16.bf16.f32 "
                        "{%0,%1,%2,%3}, {%4,%5,%6,%7}, {%8,%9}, {%0,%1,%2,%3};"
                        : "+f"(c[mt][nt][0]), "+f"(c[mt][nt][1]),
                          "+f"(c[mt][nt][2]), "+f"(c[mt][nt][3])
                        : "r"(a[0]), "r"(a[1]), "r"(a[2]), "r"(a[3]),
                          "r"(b0), "r"(b1));
                }
            }
        }

        if ((g & 7) == 7) {
            // fold this 128-col chunk into rs, reset accumulators
            int n0 = (g >> 3) * 128;
            #pragma unroll
            for (int mt = 0; mt < 2; mt++) {
                int rbase = warp_m * 32 + mt * 16 + rr;
                float fl0 = s_flw[rbase];
                float fl1 = s_flw[rbase + 8];
                #pragma unroll
                for (int nt = 0; nt < 4; nt++) {
                    #pragma unroll
                    for (int j = 0; j < 2; j++) {
                        int n = n0 + warp_n * 32 + nt * 8 + 2 * q + j;
                        float dvn = s_dv[n], vvn = s_vv[n], wcn = s_wc[n];
                        float v0 = fmaf(fl0, wcn, c[mt][nt][j] + dvn);
                        float v1 = fmaf(fl1, wcn, c[mt][nt][2 + j] + dvn);
                        rs[mt][0] += vvn * fast_tanh(v0);
                        rs[mt][1] += vvn * fast_tanh(v1);
                        c[mt][nt][j] = 0.f;
                        c[mt][nt][2 + j] = 0.f;
                    }
                }
            }
        }
    }

    // ---- final reduce: quad shuffle, smem atomic across warp_n, store ----
    #pragma unroll
    for (int mt = 0; mt < 2; mt++) {
        float r0 = rs[mt][0], r1 = rs[mt][1];
        r0 += __shfl_xor_sync(0xFFFFFFFFu, r0, 1, 4);
        r0 += __shfl_xor_sync(0xFFFFFFFFu, r0, 2, 4);
        r1 += __shfl_xor_sync(0xFFFFFFFFu, r1, 1, 4);
        r1 += __shfl_xor_sync(0xFFFFFFFFu, r1, 2, 4);
        if (q == 0) {
            int rbase = warp_m * 32 + mt * 16 + rr;
            atomicAdd(&s_red[rbase], r0);
            atomicAdd(&s_red[rbase + 8], r1);
        }
    }
    __syncthreads();
    if (tid < 128)
        (node ? g_scores_node : g_scores_tok)[m0 + tid] = s_red[tid];
}

// ---------------- block reduce helpers (1024 threads) ----------------
__device__ __forceinline__ float blockReduceMax1024(float v, float* sh) {
    #pragma unroll
    for (int off = 16; off > 0; off >>= 1)
        v = fmaxf(v, __shfl_xor_sync(0xFFFFFFFFu, v, off));
    int lane = threadIdx.x & 31, w = threadIdx.x >> 5;
    if (lane == 0) sh[w] = v;
    __syncthreads();
    if (threadIdx.x < 32) {
        float x = sh[threadIdx.x];
        #pragma unroll
        for (int off = 16; off > 0; off >>= 1)
            x = fmaxf(x, __shfl_xor_sync(0xFFFFFFFFu, x, off));
        if (threadIdx.x == 0) sh[0] = x;
    }
    __syncthreads();
    float r = sh[0];
    __syncthreads();
    return r;
}

__device__ __forceinline__ float blockReduceSum1024(float v, float* sh) {
    #pragma unroll
    for (int off = 16; off > 0; off >>= 1)
        v += __shfl_xor_sync(0xFFFFFFFFu, v, off);
    int lane = threadIdx.x & 31, w = threadIdx.x >> 5;
    if (lane == 0) sh[w] = v;
    __syncthreads();
    if (threadIdx.x < 32) {
        float x = sh[threadIdx.x];
        #pragma unroll
        for (int off = 16; off > 0; off >>= 1)
            x += __shfl_xor_sync(0xFFFFFFFFu, x, off);
        if (threadIdx.x == 0) sh[0] = x;
    }
    __syncthreads();
    float r = sh[0];
    __syncthreads();
    return r;
}

// ---------------- K3: fused post-processing, 1024 threads / batch -------------
__global__ void __launch_bounds__(1024)
post_kernel(const int* __restrict__ n2t,
            const float* __restrict__ mask_tok,
            const float* __restrict__ mask_node,
            const float* __restrict__ graph,
            float* __restrict__ d_out) {
    __shared__ float s_attn[NKN];
    __shared__ float s_hop[NKN];
    __shared__ float s_part[1024];
    __shared__ float sh[32];

    const int b = blockIdx.x, t = threadIdx.x;   // 1024 threads

    float s = (t < NKN) ? g_scores_node[b * NKN + t] : -INFINITY;
    float mk_n = (t < NKN) ? mask_node[b * NKN + t] : 0.f;
    float m = blockReduceMax1024(s, sh);
    float e = (t < NKN) ? __expf(s - m) * mk_n : 0.f;
    float sum = blockReduceSum1024(e, sh);
    float a = e / sum;
    if (t < NKN) {
        s_attn[t] = a;
        d_out[BB * HD + BB * TK + b * NKN + t] = a;   // attn_dist_node output
    }
    __syncthreads();

    float mk = 0.f, sc = -INFINITY, g = -INFINITY;
    if (t < TK) {
        mk = mask_tok[b * TK + t];
        sc = g_scores_tok[b * TK + t];
        g = s_attn[n2t[b * TK + t]];
    }
    float m1 = blockReduceMax1024(sc, sh);
    float e1 = (t < TK) ? __expf(sc - m1) * mk : 0.f;
    float s1 = blockReduceSum1024(e1, sh);

    float m2 = blockReduceMax1024(g, sh);
    float e2 = (t < TK) ? __expf(g - m2) * mk : 0.f;
    float s2 = blockReduceSum1024(e2, sh);

    if (t < TK) {
        float fin = 0.5f * (e1 / s1) + 0.5f * (e2 / s2);
        g_final[b * TK + t] = fin;
        d_out[BB * HD + b * TK + t] = fin;             // final_attn output
    }
    __syncthreads();

    const float* G = graph + (size_t)b * NKN * NKN;
    const int col = t & (NKN - 1);
    const int qr = t >> 8;                // 0..3
    float acc = 0.f;
    #pragma unroll 8
    for (int n = qr * 64; n < qr * 64 + 64; n++)
        acc = fmaf(s_attn[n], G[n * NKN + col], acc);
    s_part[t] = acc;
    __syncthreads();
    if (t < NKN)
        s_hop[t] = s_part[t] + s_part[t + 256] + s_part[t + 512] + s_part[t + 768];
    __syncthreads();

    float acc2 = 0.f;
    #pragma unroll 8
    for (int n = qr * 64; n < qr * 64 + 64; n++)
        acc2 = fmaf(s_hop[n], G[n * NKN + col], acc2);
    s_part[t] = acc2;
    __syncthreads();
    if (t < NKN) {
        float two = s_part[t] + s_part[t + 256] + s_part[t + 512] + s_part[t + 768];
        float outv = (s_attn[t] + s_hop[t] + two) * 0.33333f;
        d_out[BB * HD + BB * TK + BB * NKN + b * NKN + t] = outv;   // flow_out
    }
}

// ---------------- K4: c_t = final_attn @ enc_tok, grid (BB, 32) ---------------
__global__ void ctx_kernel(const float* __restrict__ enc_tok,
                           float* __restrict__ d_out) {
    int b = blockIdx.x, h = threadIdx.x;          // 512 threads
    int t0 = blockIdx.y * 16;
    float acc = 0.f;
    #pragma unroll
    for (int t = t0; t < t0 + 16; t++)
        acc = fmaf(g_final[b * TK + t], enc_tok[((size_t)(b * TK + t)) * HD + h], acc);
    atomicAdd(&d_out[b * HD + h], acc);           // c_t output (zeroed in convert)
}

// ---------------- launch ----------------
extern "C" void kernel_launch(void* const* d_in, const int* in_sizes, int n_in,
                              void* d_out, int out_size) {
    const float* s_t_hat   = (const float*)d_in[0];
    const float* enc_tok   = (const float*)d_in[1];
    const float* enc_node  = (const float*)d_in[2];
    const int*   n2t       = (const int*)  d_in[3];
    const float* mask_tok  = (const float*)d_in[4];
    const float* mask_node = (const float*)d_in[5];
    const float* graph     = (const float*)d_in[6];
    const float* flow      = (const float*)d_in[7];
    const float* W_c       = (const float*)d_in[8];
    const float* W_tok     = (const float*)d_in[9];
    const float* W_node    = (const float*)d_in[10];
    const float* W_dec     = (const float*)d_in[11];
    const float* b_dec     = (const float*)d_in[12];
    const float* v_tok     = (const float*)d_in[13];
    const float* v_node    = (const float*)d_in[14];
    float* out = (float*)d_out;

    static bool attr_set = false;
    if (!attr_set) {
        cudaFuncSetAttribute(gemm_score_fused,
                             cudaFuncAttributeMaxDynamicSharedMemorySize, GSMEM);
        attr_set = true;
    }

    const int CV_THREADS = 256;
    const int CV_BLOCKS = (S0 + S1 + 2 * S2) / 8 / CV_THREADS + Z_TOTAL / 8 / CV_THREADS;
    convert_kernel<<<CV_BLOCKS, CV_THREADS>>>(enc_tok, enc_node, W_tok, W_node, out);

    dec_kernel2<<<dim3(8, 8), 512>>>(s_t_hat, W_dec, b_dec);

    gemm_score_fused<<<384, 512, GSMEM>>>(flow, W_c, v_tok, v_node);

    post_kernel<<<BB, 1024>>>(n2t, mask_tok, mask_node, graph, out);

    ctx_kernel<<<dim3(BB, 32), HD>>>(enc_tok, out);
}

// round 12
// speedup vs baseline: 1.2241x; 1.2241x over previous
#include <cuda_runtime.h>
#include <math.h>
#include <stdint.h>

#define HD 512
#define BB 64
#define TK 512
#define NKN 256

// -------- scratch (device globals: no allocations allowed) --------
__device__ float g_dec[BB * HD];
__device__ float g_scores_tok[BB * TK];
__device__ float g_scores_node[BB * NKN];
__device__ float g_attn_node[BB * NKN];
__device__ float g_final[BB * TK];

// bf16 copies (packed pairs in uint32)
__device__ __align__(16) uint32_t g_bAtok[BB * TK * HD / 2];    // 33.5 MB
__device__ __align__(16) uint32_t g_bAnode[BB * NKN * HD / 2];  // 16.8 MB
__device__ __align__(16) uint32_t g_bWtok[HD * HD / 2];
__device__ __align__(16) uint32_t g_bWnode[HD * HD / 2];

__device__ __forceinline__ float fast_tanh(float x) {
    float y;
    asm("tanh.approx.f32 %0, %1;" : "=f"(y) : "f"(x));
    return y;
}

__device__ __forceinline__ uint32_t bfpack(float lo, float hi) {
    uint32_t r;
    asm("cvt.rn.bf16x2.f32 %0, %1, %2;" : "=r"(r) : "f"(hi), "f"(lo));
    return r;
}

__device__ __forceinline__ void cp16(uint32_t dst, const void* src) {
    asm volatile("cp.async.cg.shared.global [%0], [%1], 16;" :: "r"(dst), "l"(src));
}

// ---------------- K0: fp32 -> bf16 conversion + scratch zeroing ----------------
#define S0 (BB * TK * HD)     // 16777216
#define S1 (BB * NKN * HD)    // 8388608
#define S2 (HD * HD)          // 262144
#define CV_TOTAL ((size_t)S0 + S1 + 2 * S2)          // 25690112 floats
#define Z_DEC    (BB * HD)                            // 32768
#define Z_STOK   (BB * TK)                            // 32768
#define Z_SNODE  (BB * NKN)                           // 16384
#define Z_CT     (BB * HD)                            // 32768
#define Z_TOTAL  (Z_DEC + Z_STOK + Z_SNODE + Z_CT)    // 114688
__global__ void convert_kernel(const float* __restrict__ A_tok,
                               const float* __restrict__ A_node,
                               const float* __restrict__ Wt,
                               const float* __restrict__ Wn,
                               float* __restrict__ d_out) {
    size_t gid = (size_t)blockIdx.x * blockDim.x + threadIdx.x;
    size_t i8 = gid * 8;
    if (i8 >= CV_TOTAL) {
        size_t z = i8 - CV_TOTAL;
        float4 zf = make_float4(0.f, 0.f, 0.f, 0.f);
        float4* p;
        if (z < Z_DEC) p = (float4*)(g_dec + z);
        else if (z < Z_DEC + Z_STOK) p = (float4*)(g_scores_tok + (z - Z_DEC));
        else if (z < Z_DEC + Z_STOK + Z_SNODE)
            p = (float4*)(g_scores_node + (z - Z_DEC - Z_STOK));
        else p = (float4*)(d_out + (z - Z_DEC - Z_STOK - Z_SNODE));
        p[0] = zf;
        p[1] = zf;
        return;
    }
    const float4* s;
    uint4* d;
    if (i8 < S0) {
        s = (const float4*)(A_tok + i8);
        d = (uint4*)g_bAtok + (i8 >> 3);
    } else if (i8 < (size_t)S0 + S1) {
        size_t o = i8 - S0;
        s = (const float4*)(A_node + o);
        d = (uint4*)g_bAnode + (o >> 3);
    } else if (i8 < (size_t)S0 + S1 + S2) {
        size_t o = i8 - S0 - S1;
        s = (const float4*)(Wt + o);
        d = (uint4*)g_bWtok + (o >> 3);
    } else {
        size_t o = i8 - S0 - S1 - S2;
        s = (const float4*)(Wn + o);
        d = (uint4*)g_bWnode + (o >> 3);
    }
    float4 f0 = s[0], f1 = s[1];
    uint4 u;
    u.x = bfpack(f0.x, f0.y);
    u.y = bfpack(f0.z, f0.w);
    u.z = bfpack(f1.x, f1.y);
    u.w = bfpack(f1.z, f1.w);
    d[0] = u;
}

// ---------------- K1: dec_fea, k-split + batch-group ----------------
__global__ void dec_kernel2(const float* __restrict__ s_t,
                            const float* __restrict__ Wd,
                            const float* __restrict__ bd) {
    const int bg = blockIdx.x, kg = blockIdx.y;
    const int h = threadIdx.x;            // 512
    __shared__ float ss[8][128];
    for (int i = h; i < 8 * 128; i += 512) {
        int j = i >> 7, kk = i & 127;
        ss[j][kk] = s_t[(bg * 8 + j) * (2 * HD) + kg * 128 + kk];
    }
    __syncthreads();
    float acc[8];
    #pragma unroll
    for (int j = 0; j < 8; j++) acc[j] = 0.f;
    const float* Wp = Wd + (size_t)(kg * 128) * HD + h;
    #pragma unroll 4
    for (int kk = 0; kk < 128; kk++) {
        float w = Wp[(size_t)kk * HD];
        #pragma unroll
        for (int j = 0; j < 8; j++) acc[j] = fmaf(ss[j][kk], w, acc[j]);
    }
    float bias = (kg == 0) ? bd[h] : 0.f;
    #pragma unroll
    for (int j = 0; j < 8; j++)
        atomicAdd(&g_dec[(bg * 8 + j) * HD + h], acc[j] + bias);
}

// ---------------- K2: bf16 mma fused GEMM (round-10 version, reverted) --------
// grid = (4, 384): by<256 -> token M-tiles, by>=256 -> node M-tiles.
// CTA tile 128x128, BK=64 bf16, 3-stage cp.async ring, ldmatrix fragments.
__global__ void __launch_bounds__(256, 2)
gemm_score_fused(const float* __restrict__ flw,     // [B*NK]
                 const float* __restrict__ Wc,      // [512]
                 const float* __restrict__ v_tok,   // [512]
                 const float* __restrict__ v_node)  // [512]
{
    const int BK = 64, KT = HD / BK;           // 8 k-tiles
    const int STG = 3;
    const int A_BYTES = 128 * 128;             // 128 rows x 128B (64 bf16)
    const int B_BYTES = 64 * 256;              // 64 rows x 256B (128 bf16)
    const int STG_BYTES = A_BYTES + B_BYTES;   // 32768

    extern __shared__ char sm[];
    uint32_t sbase = (uint32_t)__cvta_generic_to_shared(sm);

    const int tid = threadIdx.x;
    const int lane = tid & 31, wid = tid >> 5;
    const int q = lane & 3, rr = lane >> 2;
    const int l15 = lane & 15, lh = lane >> 4;
    const int warp_m = wid & 1;        // 2 row groups of 64
    const int warp_n = wid >> 1;       // 4 col groups of 32
    const bool node = blockIdx.y >= 256;
    const int m0 = node ? (blockIdx.y - 256) * 128 : blockIdx.y * 128;
    const int n0 = blockIdx.x * 128;

    const uint16_t* gA = (const uint16_t*)(node ? g_bAnode : g_bAtok);
    const uint16_t* gW = (const uint16_t*)(node ? g_bWnode : g_bWtok);

    float c[4][4][4];
    #pragma unroll
    for (int mt = 0; mt < 4; mt++)
        #pragma unroll
        for (int nt = 0; nt < 4; nt++)
            #pragma unroll
            for (int k = 0; k < 4; k++) c[mt][nt][k] = 0.f;

    auto load_stage = [&](int kt, int s) {
        uint32_t sb = sbase + s * STG_BYTES;
        #pragma unroll
        for (int i = 0; i < 4; i++) {
            int idx = tid + i * 256;
            int r = idx >> 3, cc = idx & 7;
            uint32_t off = r * 128 + cc * 16;
            cp16(sb + (off ^ ((r & 7) << 4)),
                 gA + (size_t)(m0 + r) * HD + kt * BK + cc * 8);
        }
        #pragma unroll
        for (int i = 0; i < 4; i++) {
            int idx = tid + i * 256;
            int r = idx >> 4, cc = idx & 15;
            uint32_t off = r * 256 + cc * 16;
            cp16(sb + A_BYTES + (off ^ ((r & 15) << 4)),
                 gW + (size_t)(kt * BK + r) * HD + n0 + cc * 8);
        }
        asm volatile("cp.async.commit_group;" ::: "memory");
    };

    load_stage(0, 0);
    load_stage(1, 1);

    for (int kt = 0; kt < KT; kt++) {
        int s = kt % STG;
        if (kt < KT - 1) asm volatile("cp.async.wait_group 1;" ::: "memory");
        else             asm volatile("cp.async.wait_group 0;" ::: "memory");
        __syncthreads();
        if (kt + 2 < KT) load_stage(kt + 2, (kt + 2) % STG);

        uint32_t sA = sbase + s * STG_BYTES;
        uint32_t sB = sA + A_BYTES;

        #pragma unroll
        for (int kk = 0; kk < 4; kk++) {
            uint32_t bfr[2][4];
            int krow = kk * 16 + l15;
            uint32_t boff = (uint32_t)krow * 256 + warp_n * 64 + lh * 16;
            #pragma unroll
            for (int p = 0; p < 2; p++) {
                uint32_t addr = sB + ((boff + p * 32) ^ ((krow & 15) << 4));
                asm volatile(
                    "ldmatrix.sync.aligned.m8n8.x4.trans.shared.b16 {%0,%1,%2,%3}, [%4];"
                    : "=r"(bfr[p][0]), "=r"(bfr[p][1]),
                      "=r"(bfr[p][2]), "=r"(bfr[p][3]) : "r"(addr));
            }
            #pragma unroll
            for (int mt = 0; mt < 4; mt++) {
                int row = warp_m * 64 + mt * 16 + l15;
                uint32_t addr = sA + ((row * 128 + kk * 32 + lh * 16) ^ ((row & 7) << 4));
                uint32_t a[4];
                asm volatile(
                    "ldmatrix.sync.aligned.m8n8.x4.shared.b16 {%0,%1,%2,%3}, [%4];"
                    : "=r"(a[0]), "=r"(a[1]), "=r"(a[2]), "=r"(a[3]) : "r"(addr));
                #pragma unroll
                for (int nt = 0; nt < 4; nt++) {
                    uint32_t b0 = bfr[nt >> 1][(nt & 1) * 2];
                    uint32_t b1 = bfr[nt >> 1][(nt & 1) * 2 + 1];
                    asm volatile(
                        "mma.sync.aligned.m16n8k16.row.col.f32.bf16.bf16.f32 "
                        "{%0,%1,%2,%3}, {%4,%5,%6,%7}, {%8,%9}, {%0,%1,%2,%3};"
                        : "+f"(c[mt][nt][0]), "+f"(c[mt][nt][1]),
                          "+f"(c[mt][nt][2]), "+f"(c[mt][nt][3])
                        : "r"(a[0]), "r"(a[1]), "r"(a[2]), "r"(a[3]),
                          "r"(b0), "r"(b1));
                }
            }
        }
    }

    // ---- epilogue: tanh + v-dot, quad reduce, atomic partial scores ----
    float* scores = node ? g_scores_node : g_scores_tok;
    const float* v = node ? v_node : v_tok;
    int b = node ? (m0 / NKN) : (m0 / TK);

    float dv[8], vv[8], wc[8];
    #pragma unroll
    for (int nt = 0; nt < 4; nt++) {
        #pragma unroll
        for (int j = 0; j < 2; j++) {
            int n = n0 + warp_n * 32 + nt * 8 + 2 * q + j;
            dv[nt * 2 + j] = g_dec[b * HD + n];
            vv[nt * 2 + j] = v[n];
            wc[nt * 2 + j] = node ? Wc[n] : 0.f;
        }
    }

    #pragma unroll
    for (int mt = 0; mt < 4; mt++) {
        int r = m0 + warp_m * 64 + mt * 16 + rr;
        float fl0 = node ? flw[r] : 0.f;
        float fl1 = node ? flw[r + 8] : 0.f;
        float rs0 = 0.f, rs1 = 0.f;
        #pragma unroll
        for (int nt = 0; nt < 4; nt++) {
            #pragma unroll
            for (int j = 0; j < 2; j++) {
                int e = nt * 2 + j;
                float v0 = fmaf(fl0, wc[e], c[mt][nt][j] + dv[e]);
                float v1 = fmaf(fl1, wc[e], c[mt][nt][2 + j] + dv[e]);
                rs0 += vv[e] * fast_tanh(v0);
                rs1 += vv[e] * fast_tanh(v1);
            }
        }
        rs0 += __shfl_xor_sync(0xFFFFFFFFu, rs0, 1, 4);
        rs0 += __shfl_xor_sync(0xFFFFFFFFu, rs0, 2, 4);
        rs1 += __shfl_xor_sync(0xFFFFFFFFu, rs1, 1, 4);
        rs1 += __shfl_xor_sync(0xFFFFFFFFu, rs1, 2, 4);
        if (q == 0) {
            atomicAdd(&scores[r], rs0);
            atomicAdd(&scores[r + 8], rs1);
        }
    }
}

// ---------------- block reduce helpers (1024 threads) ----------------
__device__ __forceinline__ float blockReduceMax1024(float v, float* sh) {
    #pragma unroll
    for (int off = 16; off > 0; off >>= 1)
        v = fmaxf(v, __shfl_xor_sync(0xFFFFFFFFu, v, off));
    int lane = threadIdx.x & 31, w = threadIdx.x >> 5;
    if (lane == 0) sh[w] = v;
    __syncthreads();
    if (threadIdx.x < 32) {
        float x = sh[threadIdx.x];
        #pragma unroll
        for (int off = 16; off > 0; off >>= 1)
            x = fmaxf(x, __shfl_xor_sync(0xFFFFFFFFu, x, off));
        if (threadIdx.x == 0) sh[0] = x;
    }
    __syncthreads();
    float r = sh[0];
    __syncthreads();
    return r;
}

__device__ __forceinline__ float blockReduceSum1024(float v, float* sh) {
    #pragma unroll
    for (int off = 16; off > 0; off >>= 1)
        v += __shfl_xor_sync(0xFFFFFFFFu, v, off);
    int lane = threadIdx.x & 31, w = threadIdx.x >> 5;
    if (lane == 0) sh[w] = v;
    __syncthreads();
    if (threadIdx.x < 32) {
        float x = sh[threadIdx.x];
        #pragma unroll
        for (int off = 16; off > 0; off >>= 1)
            x += __shfl_xor_sync(0xFFFFFFFFu, x, off);
        if (threadIdx.x == 0) sh[0] = x;
    }
    __syncthreads();
    float r = sh[0];
    __syncthreads();
    return r;
}

// ---------------- K3: softmaxes + gather + mix (one block per batch) ----------
__global__ void __launch_bounds__(1024)
soft_kernel(const int* __restrict__ n2t,
            const float* __restrict__ mask_tok,
            const float* __restrict__ mask_node,
            float* __restrict__ d_out) {
    __shared__ float s_attn[NKN];
    __shared__ float sh[32];

    const int b = blockIdx.x, t = threadIdx.x;   // 1024 threads

    // node masked-renorm softmax
    float s = (t < NKN) ? g_scores_node[b * NKN + t] : -INFINITY;
    float mk_n = (t < NKN) ? mask_node[b * NKN + t] : 0.f;
    float m = blockReduceMax1024(s, sh);
    float e = (t < NKN) ? __expf(s - m) * mk_n : 0.f;
    float sum = blockReduceSum1024(e, sh);
    float a = e / sum;
    if (t < NKN) {
        s_attn[t] = a;
        g_attn_node[b * NKN + t] = a;
        d_out[BB * HD + BB * TK + b * NKN + t] = a;   // attn_dist_node output
    }
    __syncthreads();

    // gather + both token softmaxes + mix
    float mk = 0.f, sc = -INFINITY, g = -INFINITY;
    if (t < TK) {
        mk = mask_tok[b * TK + t];
        sc = g_scores_tok[b * TK + t];
        g = s_attn[n2t[b * TK + t]];
    }
    float m1 = blockReduceMax1024(sc, sh);
    float e1 = (t < TK) ? __expf(sc - m1) * mk : 0.f;
    float s1 = blockReduceSum1024(e1, sh);

    float m2 = blockReduceMax1024(g, sh);
    float e2 = (t < TK) ? __expf(g - m2) * mk : 0.f;
    float s2 = blockReduceSum1024(e2, sh);

    if (t < TK) {
        float fin = 0.5f * (e1 / s1) + 0.5f * (e2 / s2);
        g_final[b * TK + t] = fin;
        d_out[BB * HD + b * TK + t] = fin;             // final_attn output
    }
}

// ---------------- K4: tail — graph hops (blocks 0..63) + ctx (blocks 64..) ----
// One launch so hop blocks and ctx blocks overlap on different SMs.
__global__ void __launch_bounds__(1024)
tail_kernel(const float* __restrict__ graph,
            const float* __restrict__ enc_tok,
            float* __restrict__ d_out) {
    __shared__ float s_attn[NKN];
    __shared__ float s_hop[NKN];
    __shared__ float s_part[1024];

    const int t = threadIdx.x;   // 1024 threads

    if (blockIdx.x < BB) {
        // ---- graph 2-hop diffusion for batch b ----
        const int b = blockIdx.x;
        if (t < NKN) s_attn[t] = g_attn_node[b * NKN + t];
        __syncthreads();

        const float* G = graph + (size_t)b * NKN * NKN;
        const int col = t & (NKN - 1);
        const int qr = t >> 8;                // 0..3
        float acc = 0.f;
        #pragma unroll 8
        for (int n = qr * 64; n < qr * 64 + 64; n++)
            acc = fmaf(s_attn[n], G[n * NKN + col], acc);
        s_part[t] = acc;
        __syncthreads();
        if (t < NKN)
            s_hop[t] = s_part[t] + s_part[t + 256] + s_part[t + 512] + s_part[t + 768];
        __syncthreads();

        float acc2 = 0.f;
        #pragma unroll 8
        for (int n = qr * 64; n < qr * 64 + 64; n++)
            acc2 = fmaf(s_hop[n], G[n * NKN + col], acc2);
        s_part[t] = acc2;
        __syncthreads();
        if (t < NKN) {
            float two = s_part[t] + s_part[t + 256] + s_part[t + 512] + s_part[t + 768];
            float outv = (s_attn[t] + s_hop[t] + two) * 0.33333f;
            d_out[BB * HD + BB * TK + BB * NKN + b * NKN + t] = outv;   // flow_out
        }
    } else {
        // ---- ctx: c_t partial for 16 token rows ----
        const int i = blockIdx.x - BB;        // 0..2047
        const int b = i >> 5, chunk = i & 31;
        const int h = t & 511, half = t >> 9;
        const int t0 = chunk * 16 + half * 8;
        float acc = 0.f;
        #pragma unroll
        for (int tt = t0; tt < t0 + 8; tt++)
            acc = fmaf(g_final[b * TK + tt],
                       enc_tok[((size_t)(b * TK + tt)) * HD + h], acc);
        s_part[t] = acc;
        __syncthreads();
        if (t < 512)
            atomicAdd(&d_out[b * HD + t], s_part[t] + s_part[t + 512]);
    }
}

// ---------------- launch ----------------
extern "C" void kernel_launch(void* const* d_in, const int* in_sizes, int n_in,
                              void* d_out, int out_size) {
    const float* s_t_hat   = (const float*)d_in[0];
    const float* enc_tok   = (const float*)d_in[1];
    const float* enc_node  = (const float*)d_in[2];
    const int*   n2t       = (const int*)  d_in[3];
    const float* mask_tok  = (const float*)d_in[4];
    const float* mask_node = (const float*)d_in[5];
    const float* graph     = (const float*)d_in[6];
    const float* flow      = (const float*)d_in[7];
    const float* W_c       = (const float*)d_in[8];
    const float* W_tok     = (const float*)d_in[9];
    const float* W_node    = (const float*)d_in[10];
    const float* W_dec     = (const float*)d_in[11];
    const float* b_dec     = (const float*)d_in[12];
    const float* v_tok     = (const float*)d_in[13];
    const float* v_node    = (const float*)d_in[14];
    float* out = (float*)d_out;

    const int SMEM_BYTES = 3 * 32768;   // 98304
    static bool attr_set = false;
    if (!attr_set) {
        cudaFuncSetAttribute(gemm_score_fused,
                             cudaFuncAttributeMaxDynamicSharedMemorySize, SMEM_BYTES);
        attr_set = true;
    }

    const int CV_THREADS = 256;
    const int CV_BLOCKS = (S0 + S1 + 2 * S2) / 8 / CV_THREADS + Z_TOTAL / 8 / CV_THREADS;
    convert_kernel<<<CV_BLOCKS, CV_THREADS>>>(enc_tok, enc_node, W_tok, W_node, out);

    dec_kernel2<<<dim3(8, 8), 512>>>(s_t_hat, W_dec, b_dec);

    gemm_score_fused<<<dim3(HD / 128, 384), 256, SMEM_BYTES>>>(
        flow, W_c, v_tok, v_node);

    soft_kernel<<<BB, 1024>>>(n2t, mask_tok, mask_node, out);

    tail_kernel<<<BB + BB * 32, 1024>>>(graph, enc_tok, out);
}